// round 8
// baseline (speedup 1.0000x reference)
#include <cuda_runtime.h>
#include <cstdint>
#include <math.h>

#define D_MODEL 2048
#define SEQ 16
#define BATCH 256
#define TOK (BATCH * SEQ)          // 4096
#define HALF_D (D_MODEL / 2)       // 1024

// ---------------- hybrid GEMM config ----------------
#define BM 128
#define BN 128
#define BK 32
#define KTH 1664                   // K range covered by HMMA (52 tiles of 32)
#define NITER (KTH / BK)           // 52
#define KF (D_MODEL - KTH)         // 384 covered by FFMA
#define NFCH (KF / 8)              // 48 chunks of 8 k, one per iter (first 48 iters)
#define STAGES 3
#define STAGE_BYTES 32768          // HMMA: A 16K + B 16K
#define OFF_B 16384
#define FF_BYTES 8192              // FFMA: A 8x128x4 + B 8x128x4
#define FOFF0 (STAGES * STAGE_BYTES)          // 98304
#define SMEM_TOTAL (FOFF0 + STAGES * FF_BYTES) // 122880

// ---------------- device scratch ----------------
__device__ uint32_t g_xt[TOK * D_MODEL];          // tf32 K-permuted
__device__ uint32_t g_wt[3][D_MODEL * D_MODEL];
__device__ float g_xf[KF * TOK];                  // fp32, K-major: [k][token]
__device__ float g_wf[3][KF * D_MODEL];           // fp32, K-major: [k][e]
__device__ float g_q[TOK * D_MODEL];
__device__ float g_k[TOK * D_MODEL];
__device__ float g_v[TOK * D_MODEL];
__device__ float g_cosT[SEQ * HALF_D];
__device__ float g_sinT[SEQ * HALF_D];

// ---------------- helpers ----------------
__device__ __forceinline__ uint32_t smem_u32(const void* p) {
    uint32_t a;
    asm("{ .reg .u64 t; cvta.to.shared.u64 t, %1; cvt.u32.u64 %0, t; }" : "=r"(a) : "l"(p));
    return a;
}
__device__ __forceinline__ uint32_t f2tf32(float f) {
    uint32_t r;
    asm("cvt.rna.tf32.f32 %0, %1;" : "=r"(r) : "f"(f));
    return r;
}
__device__ __forceinline__ void mma_tf32(float* c, uint32_t a0, uint32_t a1,
                                         uint32_t a2, uint32_t a3,
                                         uint32_t b0, uint32_t b1) {
    asm volatile(
        "mma.sync.aligned.m16n8k8.row.col.f32.tf32.tf32.f32 "
        "{%0,%1,%2,%3}, {%4,%5,%6,%7}, {%8,%9}, {%0,%1,%2,%3};"
        : "+f"(c[0]), "+f"(c[1]), "+f"(c[2]), "+f"(c[3])
        : "r"(a0), "r"(a1), "r"(a2), "r"(a3), "r"(b0), "r"(b1));
}
__device__ __forceinline__ void cp16(uint32_t saddr, const void* gaddr) {
    asm volatile("cp.async.cg.shared.global [%0], [%1], 16;" :: "r"(saddr), "l"(gaddr));
}
#define CP_COMMIT() asm volatile("cp.async.commit_group;" ::: "memory")
#define CP_WAIT1()  asm volatile("cp.async.wait_group 1;" ::: "memory")

// ---------------- rotary tables ----------------
__global__ void rope_tables_kernel() {
    int j = blockIdx.x * blockDim.x + threadIdx.x;
    if (j >= HALF_D) return;
    double theta = pow(10000.0, -2.0 * ((double)j - 1.0) / (double)D_MODEL);
#pragma unroll
    for (int m = 0; m < SEQ; ++m) {
        double ang = (double)m * theta;
        g_cosT[m * HALF_D + j] = (float)cos(ang);
        g_sinT[m * HALF_D + j] = (float)sin(ang);
    }
}

// ---------------- convert to tf32 + permute K pairs ----------------
__global__ __launch_bounds__(256)
void convert_kernel(const float* __restrict__ in, uint32_t* __restrict__ out, int n8) {
    int i = blockIdx.x * blockDim.x + threadIdx.x;
    if (i >= n8) return;
    float4 a = ((const float4*)in)[2 * i];
    float4 b = ((const float4*)in)[2 * i + 1];
    uint4 o0, o1;
    o0.x = f2tf32(a.x); o0.y = f2tf32(b.x);
    o0.z = f2tf32(a.y); o0.w = f2tf32(b.y);
    o1.x = f2tf32(a.z); o1.y = f2tf32(b.z);
    o1.z = f2tf32(a.w); o1.w = f2tf32(b.w);
    ((uint4*)out)[2 * i]     = o0;
    ((uint4*)out)[2 * i + 1] = o1;
}

// ---------------- transpose FFMA slice to K-major fp32 ----------------
// D[k][r] = S[r][KTH + k],  k in [0, KF)
__global__ void transpose_kernel(const float* __restrict__ x,
                                 const float* __restrict__ wq,
                                 const float* __restrict__ wk,
                                 const float* __restrict__ wv) {
    __shared__ float tile[32][33];
    const int which = blockIdx.z;
    const float* S;
    float* D;
    int R;
    if (which == 0) { S = x;  D = g_xf;                 R = TOK; }
    else {
        S = (which == 1) ? wq : (which == 2) ? wk : wv;
        D = g_wf[which - 1];
        R = D_MODEL;
    }
    const int r0 = blockIdx.x * 32;
    if (r0 >= R) return;
    const int c0l = blockIdx.y * 32;           // 0..352
    const int c0  = KTH + c0l;
    const int tx = threadIdx.x, ty = threadIdx.y;
#pragma unroll
    for (int j = 0; j < 32; j += 8)
        tile[ty + j][tx] = S[(size_t)(r0 + ty + j) * D_MODEL + c0 + tx];
    __syncthreads();
#pragma unroll
    for (int j = 0; j < 32; j += 8)
        D[(size_t)(c0l + ty + j) * R + r0 + tx] = tile[tx][ty + j];
}

// ---------------- hybrid QKV GEMM (HMMA tf32 + FFMA fp32) + rotary ----------------
// grid = (16, 32, 3), block = 256 (8 warps, 4M x 2N, 32x64 warp tiles), 1 CTA/SM
__global__ __launch_bounds__(256, 1)
void qkv_gemm_kernel() {
    extern __shared__ char smem[];
    const uint32_t sb = smem_u32(smem);
    const int tid   = threadIdx.x;
    const int lane  = tid & 31;
    const int wid   = tid >> 5;
    const int warpM = wid >> 1;         // 0..3 -> 32-row slabs
    const int warpN = wid & 1;          // 0..1 -> 64-col slabs
    const int lr    = lane >> 2;        // 0..7
    const int lc    = lane & 3;         // 0..3
    const uint32_t fr = (uint32_t)(lr & 3);
    const int mat   = blockIdx.z;
    const int mBase = blockIdx.y * BM;
    const int nBase = blockIdx.x * BN;

    const uint32_t* A = g_xt;
    const uint32_t* B = g_wt[mat];
    const float* Af = g_xf;
    const float* Bf = g_wf[mat];

    float acc[2][8][4];
#pragma unroll
    for (int mt = 0; mt < 2; ++mt)
#pragma unroll
        for (int nt = 0; nt < 8; ++nt)
#pragma unroll
            for (int i = 0; i < 4; ++i) acc[mt][nt][i] = 0.f;

    float accF[8][8];
#pragma unroll
    for (int i = 0; i < 8; ++i)
#pragma unroll
        for (int j = 0; j < 8; ++j) accF[i][j] = 0.f;

    uint32_t rowA[2];
    uint32_t rowB[8];
#pragma unroll
    for (int mt = 0; mt < 2; ++mt) rowA[mt] = (uint32_t)(warpM * 32 + mt * 16 + lr) * 128u;
#pragma unroll
    for (int nt = 0; nt < 8; ++nt) rowB[nt] = (uint32_t)(warpN * 64 + nt * 8 + lr) * 128u + OFF_B;

    // FFMA consumer bases (byte offsets within an FF stage)
    const uint32_t mrF = (uint32_t)(warpM * 32 + (lane >> 3) * 8);   // 8 contiguous rows
    const uint32_t ncF = (uint32_t)(warpN * 64 + (lane & 7) * 8);    // 8 contiguous cols
    const uint32_t aFoff = mrF * 4u;
    const uint32_t bFoff = 4096u + ncF * 4u;

    auto load_stage = [&](int kt, int s) {
        if (kt < NITER) {
            const uint32_t st = sb + (uint32_t)s * STAGE_BYTES;
            const int kBase = kt * BK;
#pragma unroll
            for (int i = 0; i < 4; ++i) {           // A: 1024 16B-chunks
                const int idx = tid + i * 256;
                const int row = idx >> 3, p = idx & 7;
                const uint32_t off = (uint32_t)row * 128u + (((uint32_t)p << 4) ^ (((uint32_t)(row & 3)) << 5));
                cp16(st + off, A + (size_t)(mBase + row) * D_MODEL + kBase + p * 4);
            }
#pragma unroll
            for (int i = 0; i < 4; ++i) {           // B: 1024 16B-chunks
                const int idx = tid + i * 256;
                const int row = idx >> 3, p = idx & 7;
                const uint32_t off = (uint32_t)row * 128u + (((uint32_t)p << 4) ^ (((uint32_t)(row & 3)) << 5));
                cp16(st + OFF_B + off, B + (size_t)(nBase + row) * D_MODEL + kBase + p * 4);
            }
            if (kt < NFCH) {                         // FFMA chunk: 8 k x (128 A + 128 B)
                const uint32_t fo = sb + FOFF0 + (uint32_t)s * FF_BYTES;
                const int k = tid >> 5, seg = tid & 31;
                cp16(fo + (uint32_t)k * 512u + (uint32_t)seg * 16u,
                     Af + (size_t)(kt * 8 + k) * TOK + mBase + seg * 4);
                cp16(fo + 4096u + (uint32_t)k * 512u + (uint32_t)seg * 16u,
                     Bf + (size_t)(kt * 8 + k) * D_MODEL + nBase + seg * 4);
            }
        }
        CP_COMMIT();
    };

    load_stage(0, 0);
    load_stage(1, 1);

    for (int kt = 0; kt < NITER; ++kt) {
        CP_WAIT1();
        __syncthreads();
        load_stage(kt + 2, (kt + 2) % STAGES);

        const int s = kt % STAGES;
        const char* sA = smem + (size_t)s * STAGE_BYTES;
        const char* sF = smem + FOFF0 + (size_t)s * FF_BYTES;
        const bool doF = (kt < NFCH);

#pragma unroll
        for (int ks = 0; ks < 4; ++ks) {
            // ---- HMMA block (16 MMAs -> tensor pipe) ----
            const uint32_t off = (((uint32_t)ks ^ fr) << 5) | ((uint32_t)lc << 3);
            uint2 aF2[2][2];
#pragma unroll
            for (int mt = 0; mt < 2; ++mt) {
                aF2[mt][0] = *(const uint2*)(sA + rowA[mt] + off);
                aF2[mt][1] = *(const uint2*)(sA + rowA[mt] + 8 * 128 + off);
            }
            uint2 bF2[8];
#pragma unroll
            for (int nt = 0; nt < 8; ++nt)
                bF2[nt] = *(const uint2*)(sA + rowB[nt] + off);
#pragma unroll
            for (int mt = 0; mt < 2; ++mt)
#pragma unroll
                for (int nt = 0; nt < 8; ++nt)
                    mma_tf32(acc[mt][nt],
                             aF2[mt][0].x, aF2[mt][1].x, aF2[mt][0].y, aF2[mt][1].y,
                             bF2[nt].x, bF2[nt].y);

            // ---- FFMA block (2 k-steps -> fma pipe, overlaps tensor) ----
            if (doF) {
#pragma unroll
                for (int kk = 0; kk < 2; ++kk) {
                    const uint32_t ko = (uint32_t)(ks * 2 + kk) * 512u;
                    const float4 av0 = *(const float4*)(sF + ko + aFoff);
                    const float4 av1 = *(const float4*)(sF + ko + aFoff + 16u);
                    const float4 bv0 = *(const float4*)(sF + ko + bFoff);
                    const float4 bv1 = *(const float4*)(sF + ko + bFoff + 16u);
                    const float av[8] = {av0.x, av0.y, av0.z, av0.w, av1.x, av1.y, av1.z, av1.w};
                    const float bv[8] = {bv0.x, bv0.y, bv0.z, bv0.w, bv1.x, bv1.y, bv1.z, bv1.w};
#pragma unroll
                    for (int i = 0; i < 8; ++i)
#pragma unroll
                        for (int j = 0; j < 8; ++j)
                            accF[i][j] += av[i] * bv[j];
                }
            }
        }
    }

    // ---------------- merge accF into fragments via smem ----------------
    __syncthreads();   // all warps done reading stages; reuse stage space [0, 64K)
#pragma unroll
    for (int i = 0; i < 8; ++i) {
        *(float4*)(smem + (size_t)(mrF + i) * 512 + ncF * 4)      = *(float4*)&accF[i][0];
        *(float4*)(smem + (size_t)(mrF + i) * 512 + ncF * 4 + 16) = *(float4*)&accF[i][4];
    }
    __syncwarp();      // warp-local region: each warp reads only what it wrote

    // ---------------- epilogue: add FFMA part, rotary (q/k), store ----------------
    float* out = (mat == 0) ? g_q : (mat == 1) ? g_k : g_v;
#pragma unroll
    for (int mt = 0; mt < 2; ++mt) {
        const int rloc = warpM * 32 + mt * 16 + lr;
        const int row0 = mBase + rloc;
        const int m0 = row0 & (SEQ - 1);
        const int m1 = (row0 + 8) & (SEQ - 1);
#pragma unroll
        for (int nt = 0; nt < 8; ++nt) {
            const int cloc = warpN * 64 + nt * 8 + lc * 2;
            const int col = nBase + cloc;
            const float2 f0 = *(const float2*)(smem + (size_t)rloc * 512 + cloc * 4);
            const float2 f1 = *(const float2*)(smem + (size_t)(rloc + 8) * 512 + cloc * 4);
            float c0 = acc[mt][nt][0] + f0.x, c1 = acc[mt][nt][1] + f0.y;
            float c2 = acc[mt][nt][2] + f1.x, c3 = acc[mt][nt][3] + f1.y;
            if (mat < 2) {
                const int j = col >> 1;
                const float cs0 = g_cosT[m0 * HALF_D + j], sn0 = g_sinT[m0 * HALF_D + j];
                const float cs1 = g_cosT[m1 * HALF_D + j], sn1 = g_sinT[m1 * HALF_D + j];
                const float o0 = c0 * cs0 + c1 * sn0;
                const float o1 = c1 * cs0 - c0 * sn0;
                const float o2 = c2 * cs1 + c3 * sn1;
                const float o3 = c3 * cs1 - c2 * sn1;
                c0 = o0; c1 = o1; c2 = o2; c3 = o3;
            }
            *(float2*)(out + (size_t)row0 * D_MODEL + col)       = make_float2(c0, c1);
            *(float2*)(out + (size_t)(row0 + 8) * D_MODEL + col) = make_float2(c2, c3);
        }
    }
}

// ---------------- attention: one block per batch ----------------
__global__ __launch_bounds__(256)
void attn_kernel(float* __restrict__ out) {
    __shared__ __align__(16) float qs[16][132];
    __shared__ __align__(16) float ks[16][132];
    __shared__ float at[16][16];

    const int b   = blockIdx.x;
    const int tid = threadIdx.x;
    const float* qb = g_q + (size_t)b * SEQ * D_MODEL;
    const float* kb = g_k + (size_t)b * SEQ * D_MODEL;
    const float* vb = g_v + (size_t)b * SEQ * D_MODEL;

    const int m = tid >> 4, n = tid & 15;
    float s = 0.f;

    for (int ch = 0; ch < D_MODEL / 128; ++ch) {
        __syncthreads();
#pragma unroll
        for (int i = tid; i < 16 * 32; i += 256) {
            const int r = i >> 5, cc = (i & 31) * 4;
            *(float4*)&qs[r][cc] = *(const float4*)(qb + (size_t)r * D_MODEL + ch * 128 + cc);
            *(float4*)&ks[r][cc] = *(const float4*)(kb + (size_t)r * D_MODEL + ch * 128 + cc);
        }
        __syncthreads();
#pragma unroll
        for (int d = 0; d < 128; ++d) s += qs[m][d] * ks[n][d];
    }
    s *= rsqrtf((float)D_MODEL);

    float mx = s;
#pragma unroll
    for (int off = 8; off; off >>= 1)
        mx = fmaxf(mx, __shfl_xor_sync(0xffffffffu, mx, off, 16));
    const float p = __expf(s - mx);
    float sum = p;
#pragma unroll
    for (int off = 8; off; off >>= 1)
        sum += __shfl_xor_sync(0xffffffffu, sum, off, 16);
    at[m][n] = p / sum;
    __syncthreads();

    const int mg = tid >> 6;
    const int et = tid & 63;
    float aw[4][16];
#pragma unroll
    for (int mm = 0; mm < 4; ++mm)
#pragma unroll
        for (int nn = 0; nn < 16; ++nn) aw[mm][nn] = at[mg * 4 + mm][nn];

    float* ob = out + (size_t)b * SEQ * D_MODEL;
    for (int e = et; e < D_MODEL; e += 64) {
        float acc[4] = {0.f, 0.f, 0.f, 0.f};
#pragma unroll
        for (int nn = 0; nn < 16; ++nn) {
            const float vv = vb[(size_t)nn * D_MODEL + e];
#pragma unroll
            for (int mm = 0; mm < 4; ++mm) acc[mm] += aw[mm][nn] * vv;
        }
#pragma unroll
        for (int mm = 0; mm < 4; ++mm)
            ob[(size_t)(mg * 4 + mm) * D_MODEL + e] = acc[mm];
    }
}

// ---------------- launch ----------------
extern "C" void kernel_launch(void* const* d_in, const int* in_sizes, int n_in,
                              void* d_out, int out_size) {
    const float* x  = (const float*)d_in[0];
    const float* wq = (const float*)d_in[1];
    const float* wk = (const float*)d_in[2];
    const float* wv = (const float*)d_in[3];
    float* out = (float*)d_out;

    cudaFuncSetAttribute(qkv_gemm_kernel,
                         cudaFuncAttributeMaxDynamicSharedMemorySize, SMEM_TOTAL);

    rope_tables_kernel<<<4, 256>>>();

    uint32_t* xt; cudaGetSymbolAddress((void**)&xt, g_xt);
    uint32_t* wt; cudaGetSymbolAddress((void**)&wt, g_wt);
    const int nX8 = TOK * D_MODEL / 8;       // 1M
    const int nW8 = D_MODEL * D_MODEL / 8;   // 512K
    convert_kernel<<<(nX8 + 255) / 256, 256>>>(x, xt, nX8);
    convert_kernel<<<(nW8 + 255) / 256, 256>>>(wq, wt, nW8);
    convert_kernel<<<(nW8 + 255) / 256, 256>>>(wk, wt + (size_t)D_MODEL * D_MODEL, nW8);
    convert_kernel<<<(nW8 + 255) / 256, 256>>>(wv, wt + 2 * (size_t)D_MODEL * D_MODEL, nW8);

    transpose_kernel<<<dim3(TOK / 32, KF / 32, 4), dim3(32, 8)>>>(x, wq, wk, wv);

    dim3 grid(D_MODEL / BN, TOK / BM, 3);    // (16, 32, 3)
    qkv_gemm_kernel<<<grid, 256, SMEM_TOTAL>>>();

    attn_kernel<<<BATCH, 256>>>(out);
}

// round 10
// speedup vs baseline: 1.5409x; 1.5409x over previous
#include <cuda_runtime.h>
#include <cstdint>
#include <math.h>

#define D_MODEL 2048
#define SEQ 16
#define BATCH 256
#define TOK (BATCH * SEQ)          // 4096
#define HALF_D (D_MODEL / 2)       // 1024

// ---------------- GEMM config ----------------
#define BM 128
#define BN 64
#define BK 32
#define KTILES (D_MODEL / BK)      // 64
#define STAGES 3
#define STAGE_BYTES 24576          // A 128x32x4 = 16K, B 64x32x4 = 8K
#define OFF_B 16384
#define SMEM_TOTAL (STAGES * STAGE_BYTES)   // 73728 -> 3 CTAs/SM (216K <= 228K)

// ---------------- device scratch ----------------
// tf32-converted, K-permuted operands (pairs (k, k+4) interleaved per 8-group)
__device__ uint32_t g_xt[TOK * D_MODEL];
__device__ uint32_t g_wt[3][D_MODEL * D_MODEL];
__device__ float g_q[TOK * D_MODEL];
__device__ float g_k[TOK * D_MODEL];
__device__ float g_v[TOK * D_MODEL];
__device__ float g_cosT[SEQ * HALF_D];
__device__ float g_sinT[SEQ * HALF_D];

// ---------------- helpers ----------------
__device__ __forceinline__ uint32_t smem_u32(const void* p) {
    uint32_t a;
    asm("{ .reg .u64 t; cvta.to.shared.u64 t, %1; cvt.u32.u64 %0, t; }" : "=r"(a) : "l"(p));
    return a;
}
__device__ __forceinline__ uint32_t f2tf32(float f) {
    uint32_t r;
    asm("cvt.rna.tf32.f32 %0, %1;" : "=r"(r) : "f"(f));
    return r;
}
__device__ __forceinline__ void mma_tf32(float* c, uint32_t a0, uint32_t a1,
                                         uint32_t a2, uint32_t a3,
                                         uint32_t b0, uint32_t b1) {
    asm volatile(
        "mma.sync.aligned.m16n8k8.row.col.f32.tf32.tf32.f32 "
        "{%0,%1,%2,%3}, {%4,%5,%6,%7}, {%8,%9}, {%0,%1,%2,%3};"
        : "+f"(c[0]), "+f"(c[1]), "+f"(c[2]), "+f"(c[3])
        : "r"(a0), "r"(a1), "r"(a2), "r"(a3), "r"(b0), "r"(b1));
}
__device__ __forceinline__ void cp16(uint32_t saddr, const void* gaddr) {
    asm volatile("cp.async.cg.shared.global [%0], [%1], 16;" :: "r"(saddr), "l"(gaddr));
}
#define CP_COMMIT() asm volatile("cp.async.commit_group;" ::: "memory")
#define CP_WAIT1()  asm volatile("cp.async.wait_group 1;" ::: "memory")

// ---------------- rotary tables (float, fully parallel) ----------------
// theta = 10000^(-2(j-1)/2048); float transcendental error < 2e-5 rad << 1e-3 tol
__global__ void rope_tables_kernel() {
    int idx = blockIdx.x * blockDim.x + threadIdx.x;
    if (idx >= SEQ * HALF_D) return;
    int m = idx >> 10;
    int j = idx & (HALF_D - 1);
    float theta = powf(10000.0f, -2.0f * ((float)j - 1.0f) / (float)D_MODEL);
    float ang = (float)m * theta;
    float s, c;
    sincosf(ang, &s, &c);
    g_cosT[idx] = c;
    g_sinT[idx] = s;
}

// ---------------- convert to tf32 + permute K pairs (all 4 tensors, 1 launch) ----------------
__global__ __launch_bounds__(256)
void convert_kernel(const float* __restrict__ x, const float* __restrict__ wq,
                    const float* __restrict__ wk, const float* __restrict__ wv) {
    const int which = blockIdx.y;
    const float* in;
    uint32_t* out;
    int n8;
    if (which == 0) { in = x;  out = g_xt;    n8 = TOK * D_MODEL / 8; }
    else {
        in  = (which == 1) ? wq : (which == 2) ? wk : wv;
        out = g_wt[which - 1];
        n8  = D_MODEL * D_MODEL / 8;
    }
    int i = blockIdx.x * blockDim.x + threadIdx.x;
    if (i >= n8) return;
    float4 a = ((const float4*)in)[2 * i];
    float4 b = ((const float4*)in)[2 * i + 1];
    uint4 o0, o1;
    o0.x = f2tf32(a.x); o0.y = f2tf32(b.x);
    o0.z = f2tf32(a.y); o0.w = f2tf32(b.y);
    o1.x = f2tf32(a.z); o1.y = f2tf32(b.z);
    o1.z = f2tf32(a.w); o1.w = f2tf32(b.w);
    ((uint4*)out)[2 * i]     = o0;
    ((uint4*)out)[2 * i + 1] = o1;
}

// ---------------- QKV GEMM (tf32 mma.sync) + rotary epilogue ----------------
// grid = (2048/BN=32, 4096/BM=32, 3) = 3072 CTAs, block = 256 (8 warps, 4M x 2N,
// 32x32 warp tiles), 3 CTAs/SM: ~1% wave-quantization tail, 3-way latency hiding.
__global__ __launch_bounds__(256, 3)
void qkv_gemm_kernel() {
    extern __shared__ char smem[];
    const uint32_t sb = smem_u32(smem);
    const int tid   = threadIdx.x;
    const int lane  = tid & 31;
    const int wid   = tid >> 5;
    const int warpM = wid >> 1;         // 0..3 -> 32-row slabs
    const int warpN = wid & 1;          // 0..1 -> 32-col slabs
    const int lr    = lane >> 2;        // 0..7
    const int lc    = lane & 3;         // 0..3
    const uint32_t fr = (uint32_t)(lr & 3);
    const int mat   = blockIdx.z;
    const int mBase = blockIdx.y * BM;
    const int nBase = blockIdx.x * BN;

    const uint32_t* A = g_xt;
    const uint32_t* B = g_wt[mat];

    float acc[2][4][4];
#pragma unroll
    for (int mt = 0; mt < 2; ++mt)
#pragma unroll
        for (int nt = 0; nt < 4; ++nt)
#pragma unroll
            for (int i = 0; i < 4; ++i) acc[mt][nt][i] = 0.f;

    uint32_t rowA[2];
    uint32_t rowB[4];
#pragma unroll
    for (int mt = 0; mt < 2; ++mt) rowA[mt] = (uint32_t)(warpM * 32 + mt * 16 + lr) * 128u;
#pragma unroll
    for (int nt = 0; nt < 4; ++nt) rowB[nt] = (uint32_t)(warpN * 32 + nt * 8 + lr) * 128u + OFF_B;

    auto load_stage = [&](int kt, int s) {
        if (kt < KTILES) {
            const uint32_t st = sb + (uint32_t)s * STAGE_BYTES;
            const int kBase = kt * BK;
#pragma unroll
            for (int i = 0; i < 4; ++i) {           // A: 1024 16B-chunks
                const int idx = tid + i * 256;
                const int row = idx >> 3, p = idx & 7;
                const uint32_t off = (uint32_t)row * 128u + (((uint32_t)p << 4) ^ (((uint32_t)(row & 3)) << 5));
                cp16(st + off, A + (size_t)(mBase + row) * D_MODEL + kBase + p * 4);
            }
#pragma unroll
            for (int i = 0; i < 2; ++i) {           // B: 512 16B-chunks
                const int idx = tid + i * 256;
                const int row = idx >> 3, p = idx & 7;
                const uint32_t off = (uint32_t)row * 128u + (((uint32_t)p << 4) ^ (((uint32_t)(row & 3)) << 5));
                cp16(st + OFF_B + off, B + (size_t)(nBase + row) * D_MODEL + kBase + p * 4);
            }
        }
        CP_COMMIT();
    };

    load_stage(0, 0);
    load_stage(1, 1);

    for (int kt = 0; kt < KTILES; ++kt) {
        CP_WAIT1();
        __syncthreads();
        load_stage(kt + 2, (kt + 2) % STAGES);

        const char* sA = smem + (size_t)(kt % STAGES) * STAGE_BYTES;

#pragma unroll
        for (int ks = 0; ks < 4; ++ks) {
            const uint32_t off = (((uint32_t)ks ^ fr) << 5) | ((uint32_t)lc << 3);
            uint2 aF[2][2];
#pragma unroll
            for (int mt = 0; mt < 2; ++mt) {
                aF[mt][0] = *(const uint2*)(sA + rowA[mt] + off);
                aF[mt][1] = *(const uint2*)(sA + rowA[mt] + 8 * 128 + off);
            }
            uint2 bF[4];
#pragma unroll
            for (int nt = 0; nt < 4; ++nt)
                bF[nt] = *(const uint2*)(sA + rowB[nt] + off);
#pragma unroll
            for (int mt = 0; mt < 2; ++mt)
#pragma unroll
                for (int nt = 0; nt < 4; ++nt)
                    mma_tf32(acc[mt][nt],
                             aF[mt][0].x, aF[mt][1].x, aF[mt][0].y, aF[mt][1].y,
                             bF[nt].x, bF[nt].y);
        }
    }

    // ---------------- epilogue: rotary (q/k) + store ----------------
    float* out = (mat == 0) ? g_q : (mat == 1) ? g_k : g_v;
#pragma unroll
    for (int mt = 0; mt < 2; ++mt) {
        const int row0 = mBase + warpM * 32 + mt * 16 + lr;
        const int m0 = row0 & (SEQ - 1);
        const int m1 = (row0 + 8) & (SEQ - 1);
#pragma unroll
        for (int nt = 0; nt < 4; ++nt) {
            const int col = nBase + warpN * 32 + nt * 8 + lc * 2;
            float c0 = acc[mt][nt][0], c1 = acc[mt][nt][1];
            float c2 = acc[mt][nt][2], c3 = acc[mt][nt][3];
            if (mat < 2) {
                const int j = col >> 1;
                const float cs0 = g_cosT[m0 * HALF_D + j], sn0 = g_sinT[m0 * HALF_D + j];
                const float cs1 = g_cosT[m1 * HALF_D + j], sn1 = g_sinT[m1 * HALF_D + j];
                const float o0 = c0 * cs0 + c1 * sn0;
                const float o1 = c1 * cs0 - c0 * sn0;
                const float o2 = c2 * cs1 + c3 * sn1;
                const float o3 = c3 * cs1 - c2 * sn1;
                c0 = o0; c1 = o1; c2 = o2; c3 = o3;
            }
            *(float2*)(out + (size_t)row0 * D_MODEL + col)       = make_float2(c0, c1);
            *(float2*)(out + (size_t)(row0 + 8) * D_MODEL + col) = make_float2(c2, c3);
        }
    }
}

// ---------------- attention: one block per batch ----------------
__global__ __launch_bounds__(256)
void attn_kernel(float* __restrict__ out) {
    __shared__ __align__(16) float qs[16][132];
    __shared__ __align__(16) float ks[16][132];
    __shared__ float at[16][16];

    const int b   = blockIdx.x;
    const int tid = threadIdx.x;
    const float* qb = g_q + (size_t)b * SEQ * D_MODEL;
    const float* kb = g_k + (size_t)b * SEQ * D_MODEL;
    const float* vb = g_v + (size_t)b * SEQ * D_MODEL;

    const int m = tid >> 4, n = tid & 15;
    float s = 0.f;

    for (int ch = 0; ch < D_MODEL / 128; ++ch) {
        __syncthreads();
#pragma unroll
        for (int i = tid; i < 16 * 32; i += 256) {
            const int r = i >> 5, cc = (i & 31) * 4;
            *(float4*)&qs[r][cc] = *(const float4*)(qb + (size_t)r * D_MODEL + ch * 128 + cc);
            *(float4*)&ks[r][cc] = *(const float4*)(kb + (size_t)r * D_MODEL + ch * 128 + cc);
        }
        __syncthreads();
#pragma unroll
        for (int d = 0; d < 128; ++d) s += qs[m][d] * ks[n][d];
    }
    s *= rsqrtf((float)D_MODEL);

    float mx = s;
#pragma unroll
    for (int off = 8; off; off >>= 1)
        mx = fmaxf(mx, __shfl_xor_sync(0xffffffffu, mx, off, 16));
    const float p = __expf(s - mx);
    float sum = p;
#pragma unroll
    for (int off = 8; off; off >>= 1)
        sum += __shfl_xor_sync(0xffffffffu, sum, off, 16);
    at[m][n] = p / sum;
    __syncthreads();

    const int mg = tid >> 6;
    const int et = tid & 63;
    float aw[4][16];
#pragma unroll
    for (int mm = 0; mm < 4; ++mm)
#pragma unroll
        for (int nn = 0; nn < 16; ++nn) aw[mm][nn] = at[mg * 4 + mm][nn];

    float* ob = out + (size_t)b * SEQ * D_MODEL;
    for (int e = et; e < D_MODEL; e += 64) {
        float acc[4] = {0.f, 0.f, 0.f, 0.f};
#pragma unroll
        for (int nn = 0; nn < 16; ++nn) {
            const float vv = vb[(size_t)nn * D_MODEL + e];
#pragma unroll
            for (int mm = 0; mm < 4; ++mm) acc[mm] += aw[mm][nn] * vv;
        }
#pragma unroll
        for (int mm = 0; mm < 4; ++mm)
            ob[(size_t)(mg * 4 + mm) * D_MODEL + e] = acc[mm];
    }
}

// ---------------- launch ----------------
extern "C" void kernel_launch(void* const* d_in, const int* in_sizes, int n_in,
                              void* d_out, int out_size) {
    const float* x  = (const float*)d_in[0];
    const float* wq = (const float*)d_in[1];
    const float* wk = (const float*)d_in[2];
    const float* wv = (const float*)d_in[3];
    float* out = (float*)d_out;

    cudaFuncSetAttribute(qkv_gemm_kernel,
                         cudaFuncAttributeMaxDynamicSharedMemorySize, SMEM_TOTAL);

    rope_tables_kernel<<<(SEQ * HALF_D + 255) / 256, 256>>>();

    // one launch converts all 4 tensors (blockIdx.y selects tensor)
    convert_kernel<<<dim3(TOK * D_MODEL / 8 / 256, 4), 256>>>(x, wq, wk, wv);

    dim3 grid(D_MODEL / BN, TOK / BM, 3);    // (32, 32, 3) = 3072 CTAs
    qkv_gemm_kernel<<<grid, 256, SMEM_TOTAL>>>();

    attn_kernel<<<BATCH, 256>>>(out);
}

// round 11
// speedup vs baseline: 2.0249x; 1.3141x over previous
#include <cuda_runtime.h>
#include <cstdint>
#include <math.h>

#define D_MODEL 2048
#define SEQ 16
#define BATCH 256
#define TOK (BATCH * SEQ)          // 4096
#define HALF_D (D_MODEL / 2)       // 1024

// ---------------- GEMM config ----------------
#define BM 128
#define BN 64
#define BK 32
#define KTILES (D_MODEL / BK)      // 64
#define STAGES 3
#define STAGE_BYTES 24576          // A 128x32x4 = 16K, B 64x32x4 = 8K
#define OFF_B 16384
#define SMEM_TOTAL (STAGES * STAGE_BYTES)   // 73728 -> 3 CTAs/SM (216K <= 228K)

// ---------------- device scratch ----------------
__device__ uint32_t g_xt[TOK * D_MODEL];
__device__ uint32_t g_wt[3][D_MODEL * D_MODEL];
__device__ float g_q[TOK * D_MODEL];
__device__ float g_k[TOK * D_MODEL];
__device__ float g_v[TOK * D_MODEL];
__device__ float g_cosT[SEQ * HALF_D];
__device__ float g_sinT[SEQ * HALF_D];

// ---------------- helpers ----------------
__device__ __forceinline__ uint32_t smem_u32(const void* p) {
    uint32_t a;
    asm("{ .reg .u64 t; cvta.to.shared.u64 t, %1; cvt.u32.u64 %0, t; }" : "=r"(a) : "l"(p));
    return a;
}
__device__ __forceinline__ uint32_t f2tf32(float f) {
    uint32_t r;
    asm("cvt.rna.tf32.f32 %0, %1;" : "=r"(r) : "f"(f));
    return r;
}
__device__ __forceinline__ void mma_tf32(float* c, uint32_t a0, uint32_t a1,
                                         uint32_t a2, uint32_t a3,
                                         uint32_t b0, uint32_t b1) {
    asm volatile(
        "mma.sync.aligned.m16n8k8.row.col.f32.tf32.tf32.f32 "
        "{%0,%1,%2,%3}, {%4,%5,%6,%7}, {%8,%9}, {%0,%1,%2,%3};"
        : "+f"(c[0]), "+f"(c[1]), "+f"(c[2]), "+f"(c[3])
        : "r"(a0), "r"(a1), "r"(a2), "r"(a3), "r"(b0), "r"(b1));
}
__device__ __forceinline__ void cp16(uint32_t saddr, const void* gaddr) {
    asm volatile("cp.async.cg.shared.global [%0], [%1], 16;" :: "r"(saddr), "l"(gaddr));
}
#define CP_COMMIT() asm volatile("cp.async.commit_group;" ::: "memory")
#define CP_WAIT1()  asm volatile("cp.async.wait_group 1;" ::: "memory")

// ---------------- rotary tables (float, fully parallel) ----------------
__global__ void rope_tables_kernel() {
    int idx = blockIdx.x * blockDim.x + threadIdx.x;
    if (idx >= SEQ * HALF_D) return;
    int m = idx >> 10;
    int j = idx & (HALF_D - 1);
    float theta = powf(10000.0f, -2.0f * ((float)j - 1.0f) / (float)D_MODEL);
    float ang = (float)m * theta;
    float s, c;
    sincosf(ang, &s, &c);
    g_cosT[idx] = c;
    g_sinT[idx] = s;
}

// ---------------- convert to tf32 + permute K pairs (all 4 tensors, 1 launch) ----------------
__global__ __launch_bounds__(256)
void convert_kernel(const float* __restrict__ x, const float* __restrict__ wq,
                    const float* __restrict__ wk, const float* __restrict__ wv) {
    const int which = blockIdx.y;
    const float* in;
    uint32_t* out;
    int n8;
    if (which == 0) { in = x;  out = g_xt;    n8 = TOK * D_MODEL / 8; }
    else {
        in  = (which == 1) ? wq : (which == 2) ? wk : wv;
        out = g_wt[which - 1];
        n8  = D_MODEL * D_MODEL / 8;
    }
    int i = blockIdx.x * blockDim.x + threadIdx.x;
    if (i >= n8) return;
    float4 a = ((const float4*)in)[2 * i];
    float4 b = ((const float4*)in)[2 * i + 1];
    uint4 o0, o1;
    o0.x = f2tf32(a.x); o0.y = f2tf32(b.x);
    o0.z = f2tf32(a.y); o0.w = f2tf32(b.y);
    o1.x = f2tf32(a.z); o1.y = f2tf32(b.z);
    o1.z = f2tf32(a.w); o1.w = f2tf32(b.w);
    ((uint4*)out)[2 * i]     = o0;
    ((uint4*)out)[2 * i + 1] = o1;
}

// ---------------- QKV GEMM (tf32 mma.sync) + rotary epilogue ----------------
// grid = (32, 32, 3) = 3072 CTAs, block = 256, 3 CTAs/SM  (unchanged from R10 win)
__global__ __launch_bounds__(256, 3)
void qkv_gemm_kernel() {
    extern __shared__ char smem[];
    const uint32_t sb = smem_u32(smem);
    const int tid   = threadIdx.x;
    const int lane  = tid & 31;
    const int wid   = tid >> 5;
    const int warpM = wid >> 1;
    const int warpN = wid & 1;
    const int lr    = lane >> 2;
    const int lc    = lane & 3;
    const uint32_t fr = (uint32_t)(lr & 3);
    const int mat   = blockIdx.z;
    const int mBase = blockIdx.y * BM;
    const int nBase = blockIdx.x * BN;

    const uint32_t* A = g_xt;
    const uint32_t* B = g_wt[mat];

    float acc[2][4][4];
#pragma unroll
    for (int mt = 0; mt < 2; ++mt)
#pragma unroll
        for (int nt = 0; nt < 4; ++nt)
#pragma unroll
            for (int i = 0; i < 4; ++i) acc[mt][nt][i] = 0.f;

    uint32_t rowA[2];
    uint32_t rowB[4];
#pragma unroll
    for (int mt = 0; mt < 2; ++mt) rowA[mt] = (uint32_t)(warpM * 32 + mt * 16 + lr) * 128u;
#pragma unroll
    for (int nt = 0; nt < 4; ++nt) rowB[nt] = (uint32_t)(warpN * 32 + nt * 8 + lr) * 128u + OFF_B;

    auto load_stage = [&](int kt, int s) {
        if (kt < KTILES) {
            const uint32_t st = sb + (uint32_t)s * STAGE_BYTES;
            const int kBase = kt * BK;
#pragma unroll
            for (int i = 0; i < 4; ++i) {
                const int idx = tid + i * 256;
                const int row = idx >> 3, p = idx & 7;
                const uint32_t off = (uint32_t)row * 128u + (((uint32_t)p << 4) ^ (((uint32_t)(row & 3)) << 5));
                cp16(st + off, A + (size_t)(mBase + row) * D_MODEL + kBase + p * 4);
            }
#pragma unroll
            for (int i = 0; i < 2; ++i) {
                const int idx = tid + i * 256;
                const int row = idx >> 3, p = idx & 7;
                const uint32_t off = (uint32_t)row * 128u + (((uint32_t)p << 4) ^ (((uint32_t)(row & 3)) << 5));
                cp16(st + OFF_B + off, B + (size_t)(nBase + row) * D_MODEL + kBase + p * 4);
            }
        }
        CP_COMMIT();
    };

    load_stage(0, 0);
    load_stage(1, 1);

    for (int kt = 0; kt < KTILES; ++kt) {
        CP_WAIT1();
        __syncthreads();
        load_stage(kt + 2, (kt + 2) % STAGES);

        const char* sA = smem + (size_t)(kt % STAGES) * STAGE_BYTES;

#pragma unroll
        for (int ks = 0; ks < 4; ++ks) {
            const uint32_t off = (((uint32_t)ks ^ fr) << 5) | ((uint32_t)lc << 3);
            uint2 aF[2][2];
#pragma unroll
            for (int mt = 0; mt < 2; ++mt) {
                aF[mt][0] = *(const uint2*)(sA + rowA[mt] + off);
                aF[mt][1] = *(const uint2*)(sA + rowA[mt] + 8 * 128 + off);
            }
            uint2 bF[4];
#pragma unroll
            for (int nt = 0; nt < 4; ++nt)
                bF[nt] = *(const uint2*)(sA + rowB[nt] + off);
#pragma unroll
            for (int mt = 0; mt < 2; ++mt)
#pragma unroll
                for (int nt = 0; nt < 4; ++nt)
                    mma_tf32(acc[mt][nt],
                             aF[mt][0].x, aF[mt][1].x, aF[mt][0].y, aF[mt][1].y,
                             bF[nt].x, bF[nt].y);
        }
    }

    float* out = (mat == 0) ? g_q : (mat == 1) ? g_k : g_v;
#pragma unroll
    for (int mt = 0; mt < 2; ++mt) {
        const int row0 = mBase + warpM * 32 + mt * 16 + lr;
        const int m0 = row0 & (SEQ - 1);
        const int m1 = (row0 + 8) & (SEQ - 1);
#pragma unroll
        for (int nt = 0; nt < 4; ++nt) {
            const int col = nBase + warpN * 32 + nt * 8 + lc * 2;
            float c0 = acc[mt][nt][0], c1 = acc[mt][nt][1];
            float c2 = acc[mt][nt][2], c3 = acc[mt][nt][3];
            if (mat < 2) {
                const int j = col >> 1;
                const float cs0 = g_cosT[m0 * HALF_D + j], sn0 = g_sinT[m0 * HALF_D + j];
                const float cs1 = g_cosT[m1 * HALF_D + j], sn1 = g_sinT[m1 * HALF_D + j];
                const float o0 = c0 * cs0 + c1 * sn0;
                const float o1 = c1 * cs0 - c0 * sn0;
                const float o2 = c2 * cs1 + c3 * sn1;
                const float o3 = c3 * cs1 - c2 * sn1;
                c0 = o0; c1 = o1; c2 = o2; c3 = o3;
            }
            *(float2*)(out + (size_t)row0 * D_MODEL + col)       = make_float2(c0, c1);
            *(float2*)(out + (size_t)(row0 + 8) * D_MODEL + col) = make_float2(c2, c3);
        }
    }
}

// ---------------- attention v2: coalesced, warp-per-row scores + float4 AV ----------------
// one block per batch, 512 threads (16 warps). Warp m: q-row in regs, 16 k-dots via
// LDG.128 + shuffle reduce; in-register softmax -> smem. AV: thread t owns float4
// column t (512*4 = 2048), 16 coalesced v-row loads, 16x16 float4 FMA, 16 stores.
__global__ __launch_bounds__(512)
void attn_kernel(float* __restrict__ out) {
    __shared__ float at[16][16];

    const int b    = blockIdx.x;
    const int tid  = threadIdx.x;
    const int wid  = tid >> 5;          // 0..15 = score row m
    const int lane = tid & 31;
    const float* qb = g_q + (size_t)b * SEQ * D_MODEL;
    const float* kb = g_k + (size_t)b * SEQ * D_MODEL;
    const float* vb = g_v + (size_t)b * SEQ * D_MODEL;

    // ---- scores: warp wid computes row m = wid ----
    float4 qv[16];
    {
        const float4* qrow = (const float4*)(qb + (size_t)wid * D_MODEL);
#pragma unroll
        for (int i = 0; i < 16; ++i) qv[i] = qrow[lane + i * 32];
    }
    float s[16];
#pragma unroll
    for (int n = 0; n < 16; ++n) {
        const float4* krow = (const float4*)(kb + (size_t)n * D_MODEL);
        float acc = 0.f;
#pragma unroll
        for (int i = 0; i < 16; ++i) {
            const float4 kv = krow[lane + i * 32];
            acc += qv[i].x * kv.x + qv[i].y * kv.y + qv[i].z * kv.z + qv[i].w * kv.w;
        }
#pragma unroll
        for (int off = 16; off; off >>= 1)
            acc += __shfl_xor_sync(0xffffffffu, acc, off);
        s[n] = acc;
    }
    // softmax over n (all lanes hold identical s[]; lane 0 writes)
    {
        const float scale = rsqrtf((float)D_MODEL);
        float mx = -1e30f;
#pragma unroll
        for (int n = 0; n < 16; ++n) { s[n] *= scale; mx = fmaxf(mx, s[n]); }
        float sum = 0.f;
#pragma unroll
        for (int n = 0; n < 16; ++n) { s[n] = __expf(s[n] - mx); sum += s[n]; }
        const float inv = 1.f / sum;
        if (lane < 16) at[wid][lane] = s[lane] * inv;
    }
    __syncthreads();

    // ---- AV: thread tid owns float4 column tid ----
    float w[16];
#pragma unroll
    for (int n = 0; n < 16; ++n) w[n] = 0.f;   // placeholder; loaded per m below

    float* ob = out + (size_t)b * SEQ * D_MODEL;
    float4 acc[16];
#pragma unroll
    for (int m = 0; m < 16; ++m) acc[m] = make_float4(0.f, 0.f, 0.f, 0.f);

#pragma unroll
    for (int n = 0; n < 16; ++n) {
        const float4 vv = ((const float4*)(vb + (size_t)n * D_MODEL))[tid];
#pragma unroll
        for (int m = 0; m < 16; ++m) {
            const float wt = at[m][n];
            acc[m].x += wt * vv.x;
            acc[m].y += wt * vv.y;
            acc[m].z += wt * vv.z;
            acc[m].w += wt * vv.w;
        }
    }
#pragma unroll
    for (int m = 0; m < 16; ++m)
        ((float4*)(ob + (size_t)m * D_MODEL))[tid] = acc[m];
}

// ---------------- launch ----------------
extern "C" void kernel_launch(void* const* d_in, const int* in_sizes, int n_in,
                              void* d_out, int out_size) {
    const float* x  = (const float*)d_in[0];
    const float* wq = (const float*)d_in[1];
    const float* wk = (const float*)d_in[2];
    const float* wv = (const float*)d_in[3];
    float* out = (float*)d_out;

    cudaFuncSetAttribute(qkv_gemm_kernel,
                         cudaFuncAttributeMaxDynamicSharedMemorySize, SMEM_TOTAL);

    rope_tables_kernel<<<(SEQ * HALF_D + 255) / 256, 256>>>();

    convert_kernel<<<dim3(TOK * D_MODEL / 8 / 256, 4), 256>>>(x, wq, wk, wv);

    dim3 grid(D_MODEL / BN, TOK / BM, 3);    // (32, 32, 3) = 3072 CTAs
    qkv_gemm_kernel<<<grid, 256, SMEM_TOTAL>>>();

    attn_kernel<<<BATCH, 512>>>(out);
}